// round 5
// baseline (speedup 1.0000x reference)
#include <cuda_runtime.h>

#define B_ 16
#define T_ 512
#define D_ 1024
#define N_ 16
#define SCALE 0.03125f   // 1/sqrt(1024)

#define NBLK 128
#define NTHR 256

// ---------------- device scratch (no allocations allowed) ----------------
__device__ __align__(16) float g_xz[B_ * T_ * 2 * D_];     // 64 MB: [b, t, 2D] = x_proj | z
__device__ __align__(16) float g_tape[B_ * N_ * D_];       // working tape
__device__ __align__(16) float g_hwork[2][B_ * D_];        // parity-buffered h_work
__device__ __align__(16) float g_wval[B_ * D_];            // write_val
__device__ __align__(16) float g_rs[2][B_ * N_];           // read scores (raw dots), parity
__device__ __align__(16) float g_ws[2][B_ * N_];           // write scores (raw dots), parity
__device__ unsigned int g_bar;

// ---------------- grid barrier (monotonic counter, nanosleep back-off) ----------------
// 128 CTAs, 256 thr, 1 CTA/SM: all co-resident in wave 1 on 148 SMs -> cannot starve.
__device__ __forceinline__ void grid_sync(unsigned int* nbar) {
    __syncthreads();
    if (threadIdx.x == 0) {
        *nbar += 1;
        const unsigned int target = (*nbar) * (unsigned int)NBLK;
        __threadfence();                       // push my writes to L2, flush L1 (CCTL.IVALL)
        atomicAdd(&g_bar, 1u);
        while (*((volatile unsigned int*)&g_bar) < target) { __nanosleep(32); }
        __threadfence();                       // invalidate L1 before reading peers' data
    }
    __syncthreads();
}

// ---------------- init: copy state, initial read scores, zero accumulators, reset barrier ----------------
__global__ void init_kernel(const float* __restrict__ tape_init,
                            const float* __restrict__ hwork_init) {
    const int p = blockIdx.x;          // 0..255 = b*16+n
    const int tid = threadIdx.x;       // 128 threads
    __shared__ float red[128];
    const int b = p >> 4;
    float part = 0.f;
    for (int i = tid; i < D_; i += 128) {
        const float v = tape_init[p * D_ + i];
        g_tape[p * D_ + i] = v;
        part += v * hwork_init[b * D_ + i];
    }
    red[tid] = part;
    __syncthreads();
    for (int s = 64; s; s >>= 1) { if (tid < s) red[tid] += red[tid + s]; __syncthreads(); }
    if (tid == 0) g_rs[0][p] = red[0];
    if (p < B_) {
        for (int i = tid; i < D_; i += 128) g_hwork[0][p * D_ + i] = hwork_init[p * D_ + i];
    }
    if (p == 0) {
        if (tid == 0) g_bar = 0u;      // reset barrier counter on every graph replay
        for (int i = tid; i < B_ * N_; i += 128) {
            g_rs[1][i] = 0.f; g_ws[0][i] = 0.f; g_ws[1][i] = 0.f;
        }
    }
}

// ---------------- xz = x @ W_xz^T : [8192,1024] x [2048,1024]^T -> [8192,2048] ----------------
__global__ void __launch_bounds__(256, 2) xz_gemm(const float* __restrict__ A,
                                                  const float* __restrict__ Bw) {
    __shared__ float As[8][128];
    __shared__ float Bs[8][128];
    const int tid = threadIdx.x;
    const int tx = tid & 15, ty = tid >> 4;
    const int mBase = blockIdx.y * 128, nBase = blockIdx.x * 128;
    const int lr = tid >> 1;
    const int lc = (tid & 1) << 2;
    float acc[8][8];
#pragma unroll
    for (int i = 0; i < 8; i++)
#pragma unroll
        for (int j = 0; j < 8; j++) acc[i][j] = 0.f;

    const float* Aptr = A + (mBase + lr) * 1024 + lc;
    const float* Bptr = Bw + (nBase + lr) * 1024 + lc;

    for (int k0 = 0; k0 < 1024; k0 += 8) {
        const float4 a4 = *(const float4*)(Aptr + k0);
        const float4 b4 = *(const float4*)(Bptr + k0);
        As[lc + 0][lr] = a4.x; As[lc + 1][lr] = a4.y; As[lc + 2][lr] = a4.z; As[lc + 3][lr] = a4.w;
        Bs[lc + 0][lr] = b4.x; Bs[lc + 1][lr] = b4.y; Bs[lc + 2][lr] = b4.z; Bs[lc + 3][lr] = b4.w;
        __syncthreads();
#pragma unroll
        for (int kk = 0; kk < 8; kk++) {
            float ar[8], br[8];
#pragma unroll
            for (int i = 0; i < 8; i++) { ar[i] = As[kk][ty * 8 + i]; br[i] = Bs[kk][tx * 8 + i]; }
#pragma unroll
            for (int i = 0; i < 8; i++)
#pragma unroll
                for (int j = 0; j < 8; j++) acc[i][j] = fmaf(ar[i], br[j], acc[i][j]);
        }
        __syncthreads();
    }
#pragma unroll
    for (int i = 0; i < 8; i++) {
        const int m = mBase + ty * 8 + i;
        float4* dst = (float4*)(g_xz + m * 2048 + nBase + tx * 8);
        float4 v0, v1;
        v0.x = acc[i][0]; v0.y = acc[i][1]; v0.z = acc[i][2]; v0.w = acc[i][3];
        v1.x = acc[i][4]; v1.y = acc[i][5]; v1.z = acc[i][6]; v1.w = acc[i][7];
        dst[0] = v0; dst[1] = v1;
    }
}

// ---------------- per-step recurrent GEMM: out[16b x 8d] for block's 8 rows ----------------
// warp w: row-group rg = w>>1 (2 rows), batch half bh = (w&1)*8 (8 batches)
__device__ __forceinline__ void gemm_rows(const float* __restrict__ W,
                                          const float* __restrict__ hw,
                                          int r0, float* sm_out) {
    const int tid = threadIdx.x;
    const int lane = tid & 31;
    const int wid = tid >> 5;
    const int rg = wid >> 1;
    const int bhalf = (wid & 1) << 3;
    const int d0 = r0 + rg * 2;
    const float4* W0 = (const float4*)(W + d0 * D_);
    const float4* W1 = (const float4*)(W + (d0 + 1) * D_);
    const float4* H4 = (const float4*)hw;
    float acc0[8], acc1[8];
#pragma unroll
    for (int i = 0; i < 8; i++) { acc0[i] = 0.f; acc1[i] = 0.f; }
#pragma unroll
    for (int it = 0; it < 8; it++) {
        const int j = lane + (it << 5);
        const float4 w0 = W0[j];
        const float4 w1 = W1[j];
#pragma unroll
        for (int bb = 0; bb < 8; bb++) {
            const float4 h = H4[(bhalf + bb) * 256 + j];
            acc0[bb] = fmaf(w0.x, h.x, fmaf(w0.y, h.y, fmaf(w0.z, h.z, fmaf(w0.w, h.w, acc0[bb]))));
            acc1[bb] = fmaf(w1.x, h.x, fmaf(w1.y, h.y, fmaf(w1.z, h.z, fmaf(w1.w, h.w, acc1[bb]))));
        }
    }
#pragma unroll
    for (int off = 16; off; off >>= 1) {
#pragma unroll
        for (int bb = 0; bb < 8; bb++) {
            acc0[bb] += __shfl_xor_sync(0xffffffffu, acc0[bb], off);
            acc1[bb] += __shfl_xor_sync(0xffffffffu, acc1[bb], off);
        }
    }
    if (lane < 16) {
        const int rr = lane >> 3;
        const int bb = lane & 7;
        sm_out[(rg * 2 + rr) * 16 + bhalf + bb] = rr ? acc1[bb] : acc0[bb];
    }
}

__device__ __forceinline__ void softmax16_to_smem(const float* __restrict__ scores,
                                                  float* sm_attn) {
    // threads 0..15: one batch each
    const int b = threadIdx.x;
    float s[16];
    float m = -1e30f;
#pragma unroll
    for (int n = 0; n < 16; n++) { s[n] = scores[b * 16 + n] * SCALE; m = fmaxf(m, s[n]); }
    float sum = 0.f;
#pragma unroll
    for (int n = 0; n < 16; n++) { s[n] = __expf(s[n] - m); sum += s[n]; }
    const float inv = 1.f / sum;
#pragma unroll
    for (int n = 0; n < 16; n++) sm_attn[b * 16 + n] = s[n] * inv;
}

// ---------------- persistent scan kernel ----------------
__global__ void __launch_bounds__(NTHR, 1) scan_kernel(const float* __restrict__ Wh,
                                                       const float* __restrict__ Wwr,
                                                       const float* __restrict__ bh,
                                                       float* __restrict__ out) {
    const int tid = threadIdx.x;
    const int bid = blockIdx.x;
    const int lane = tid & 31;
    const int r0 = bid * 8;       // this block's 8 d-rows

    __shared__ float attn_s[256];  // read attn (P2) then write attn (P4)
    __shared__ float sm_out[128];  // 8 rows x 16 batches GEMM results
    __shared__ float sm_ws[256];   // per-block write-score partials

    unsigned int nbar = 0;

    for (int t = 0; t < T_; t++) {
        const int cur = t & 1;
        const int nxt = cur ^ 1;

        // ================= P2: read-attn + GEMM1 + activations + output =================
        if (tid < 16) softmax16_to_smem(g_rs[cur], attn_s);
        if (bid == 0) g_ws[nxt][tid] = 0.f;    // prepare ws buffer for step t+1 accumulation
        __syncthreads();

        gemm_rows(Wh, g_hwork[cur], r0, sm_out);
        __syncthreads();

        if (tid < 128) {
            const int dl = tid >> 4, b = tid & 15;
            const int d = r0 + dl;
            const float sum = sm_out[dl * 16 + b];
            float rv = 0.f;
#pragma unroll
            for (int n = 0; n < 16; n++)
                rv = fmaf(attn_s[b * 16 + n], g_tape[(b * 16 + n) * D_ + d], rv);
            const float xp = g_xz[(b * T_ + t) * (2 * D_) + d];
            const float pre = xp + sum + rv + bh[d];
            const float hnew = tanhf(pre);
            g_hwork[nxt][b * D_ + d] = hnew;
            const float z = g_xz[(b * T_ + t) * (2 * D_) + D_ + d];
            const float u = z + rv + hnew;
            const float gate = u / (1.f + __expf(-u));
            out[(b * T_ + t) * D_ + d] = hnew * gate;
        }
        grid_sync(&nbar);

        // ================= P3: GEMM2 (write_val) + write-score partials =================
        sm_ws[tid] = 0.f;
        __syncthreads();

        gemm_rows(Wwr, g_hwork[nxt], r0, sm_out);
        __syncthreads();

        if (tid < 128) {
            const int dl = tid >> 4, b = tid & 15;
            const int d = r0 + dl;
            const float wv = sm_out[dl * 16 + b];
            g_wval[b * D_ + d] = wv;
#pragma unroll
            for (int n = 0; n < 16; n++)
                atomicAdd(&sm_ws[b * 16 + n], wv * g_tape[(b * 16 + n) * D_ + d]);
        }
        if (bid == 0) g_rs[cur][tid] = 0.f;    // prepare rs buffer for step t+1's accumulation
        __syncthreads();
        atomicAdd(&g_ws[cur][tid], sm_ws[tid]);
        grid_sync(&nbar);

        // ================= P4: write-attn softmax + tape update + next read scores =================
        if (tid < 16) softmax16_to_smem(g_ws[cur], attn_s);
        __syncthreads();

        {
            float4* tape4 = (float4*)g_tape;
            const float4* wval4 = (const float4*)g_wval;
            const float4* hw4 = (const float4*)g_hwork[nxt];
#pragma unroll
            for (int rep = 0; rep < 2; rep++) {
                const int idx = rep * (NBLK * NTHR) + bid * NTHR + tid;  // 0..65535 float4s
                const int bn = idx >> 8;          // warp-uniform
                const int b = bn >> 4;
                const int c = idx & 255;
                const float4 tv = tape4[idx];
                const float wa = attn_s[bn];
                const float4 wv = wval4[b * 256 + c];
                float4 nv;
                nv.x = tv.x + wa * (wv.x - tv.x);
                nv.y = tv.y + wa * (wv.y - tv.y);
                nv.z = tv.z + wa * (wv.z - tv.z);
                nv.w = tv.w + wa * (wv.w - tv.w);
                tape4[idx] = nv;
                const float4 h = hw4[b * 256 + c];
                float part = h.x * nv.x + h.y * nv.y + h.z * nv.z + h.w * nv.w;
#pragma unroll
                for (int off = 16; off; off >>= 1)
                    part += __shfl_xor_sync(0xffffffffu, part, off);
                if (lane == 0) atomicAdd(&g_rs[nxt][bn], part);
            }
        }
        grid_sync(&nbar);
    }

    // ---- h_tape_final: appended after output_all ----
    {
        float4* dst = (float4*)(out + B_ * T_ * D_);
        const float4* src = (const float4*)g_tape;
        for (int i = bid * NTHR + tid; i < (B_ * N_ * D_) / 4; i += NBLK * NTHR)
            dst[i] = src[i];
    }
}

// ---------------- launch (4 graph nodes total) ----------------
extern "C" void kernel_launch(void* const* d_in, const int* in_sizes, int n_in,
                              void* d_out, int out_size) {
    const float* x          = (const float*)d_in[0];
    const float* tape_init  = (const float*)d_in[1];
    const float* hwork_init = (const float*)d_in[2];
    const float* Wh         = (const float*)d_in[3];
    const float* Wxz        = (const float*)d_in[4];
    const float* bh         = (const float*)d_in[5];
    const float* Wwr        = (const float*)d_in[6];
    float* out = (float*)d_out;

    init_kernel<<<B_ * N_, 128>>>(tape_init, hwork_init);

    dim3 gg(2 * D_ / 128, (B_ * T_) / 128);   // (16, 64)
    xz_gemm<<<gg, 256>>>(x, Wxz);

    scan_kernel<<<NBLK, NTHR>>>(Wh, Wwr, bh, out);
}

// round 7
// speedup vs baseline: 1.0206x; 1.0206x over previous
#include <cuda_runtime.h>

#define B_ 16
#define T_ 512
#define D_ 1024
#define N_ 16
#define SCALE 0.03125f   // 1/sqrt(1024)

#define NBLK 128
#define NTHR 256
#define W_SMEM_BYTES (2 * 8 * D_ * 4)   // 64 KB: 8 rows Wh + 8 rows Wwr

// ---------------- device scratch (no allocations allowed) ----------------
__device__ __align__(16) float g_xz[B_ * T_ * 2 * D_];     // 64 MB: [b, t, 2D] = x_proj | z
__device__ __align__(16) float g_tape[B_ * N_ * D_];       // working tape
__device__ __align__(16) float g_hwork[2][B_ * D_];        // parity-buffered h_work
__device__ __align__(16) float g_wval[B_ * D_];            // write_val
__device__ __align__(16) float g_rs[2][B_ * N_];           // read scores (raw dots), parity
__device__ __align__(16) float g_ws[2][B_ * N_];           // write scores (raw dots), parity
__device__ unsigned int g_bar;

// ---------------- grid barrier (monotonic counter, nanosleep back-off) ----------------
// 128 CTAs, 256 thr, 1 CTA/SM: all co-resident in wave 1 on 148 SMs -> cannot starve.
__device__ __forceinline__ void grid_sync(unsigned int* nbar) {
    __syncthreads();
    if (threadIdx.x == 0) {
        *nbar += 1;
        const unsigned int target = (*nbar) * (unsigned int)NBLK;
        __threadfence();                       // push my writes to L2, flush L1 (CCTL.IVALL)
        atomicAdd(&g_bar, 1u);
        if (*((volatile unsigned int*)&g_bar) < target) {
            while (*((volatile unsigned int*)&g_bar) < target) { __nanosleep(32); }
        }
        __threadfence();                       // invalidate L1 before reading peers' data
    }
    __syncthreads();
}

// ---------------- init: copy state, initial read scores, zero accumulators, reset barrier ----------------
__global__ void init_kernel(const float* __restrict__ tape_init,
                            const float* __restrict__ hwork_init) {
    const int p = blockIdx.x;          // 0..255 = b*16+n
    const int tid = threadIdx.x;       // 128 threads
    __shared__ float red[128];
    const int b = p >> 4;
    float part = 0.f;
    for (int i = tid; i < D_; i += 128) {
        const float v = tape_init[p * D_ + i];
        g_tape[p * D_ + i] = v;
        part += v * hwork_init[b * D_ + i];
    }
    red[tid] = part;
    __syncthreads();
    for (int s = 64; s; s >>= 1) { if (tid < s) red[tid] += red[tid + s]; __syncthreads(); }
    if (tid == 0) g_rs[0][p] = red[0];
    if (p < B_) {
        for (int i = tid; i < D_; i += 128) g_hwork[0][p * D_ + i] = hwork_init[p * D_ + i];
    }
    if (p == 0) {
        if (tid == 0) g_bar = 0u;      // reset barrier counter on every graph replay
        for (int i = tid; i < B_ * N_; i += 128) {
            g_rs[1][i] = 0.f; g_ws[0][i] = 0.f; g_ws[1][i] = 0.f;
        }
    }
}

// ---------------- xz = x @ W_xz^T : [8192,1024] x [2048,1024]^T -> [8192,2048] ----------------
__global__ void __launch_bounds__(256, 2) xz_gemm(const float* __restrict__ A,
                                                  const float* __restrict__ Bw) {
    __shared__ float As[8][128];
    __shared__ float Bs[8][128];
    const int tid = threadIdx.x;
    const int tx = tid & 15, ty = tid >> 4;
    const int mBase = blockIdx.y * 128, nBase = blockIdx.x * 128;
    const int lr = tid >> 1;
    const int lc = (tid & 1) << 2;
    float acc[8][8];
#pragma unroll
    for (int i = 0; i < 8; i++)
#pragma unroll
        for (int j = 0; j < 8; j++) acc[i][j] = 0.f;

    const float* Aptr = A + (mBase + lr) * 1024 + lc;
    const float* Bptr = Bw + (nBase + lr) * 1024 + lc;

    for (int k0 = 0; k0 < 1024; k0 += 8) {
        const float4 a4 = *(const float4*)(Aptr + k0);
        const float4 b4 = *(const float4*)(Bptr + k0);
        As[lc + 0][lr] = a4.x; As[lc + 1][lr] = a4.y; As[lc + 2][lr] = a4.z; As[lc + 3][lr] = a4.w;
        Bs[lc + 0][lr] = b4.x; Bs[lc + 1][lr] = b4.y; Bs[lc + 2][lr] = b4.z; Bs[lc + 3][lr] = b4.w;
        __syncthreads();
#pragma unroll
        for (int kk = 0; kk < 8; kk++) {
            float ar[8], br[8];
#pragma unroll
            for (int i = 0; i < 8; i++) { ar[i] = As[kk][ty * 8 + i]; br[i] = Bs[kk][tx * 8 + i]; }
#pragma unroll
            for (int i = 0; i < 8; i++)
#pragma unroll
                for (int j = 0; j < 8; j++) acc[i][j] = fmaf(ar[i], br[j], acc[i][j]);
        }
        __syncthreads();
    }
#pragma unroll
    for (int i = 0; i < 8; i++) {
        const int m = mBase + ty * 8 + i;
        float4* dst = (float4*)(g_xz + m * 2048 + nBase + tx * 8);
        float4 v0, v1;
        v0.x = acc[i][0]; v0.y = acc[i][1]; v0.z = acc[i][2]; v0.w = acc[i][3];
        v1.x = acc[i][4]; v1.y = acc[i][5]; v1.z = acc[i][6]; v1.w = acc[i][7];
        dst[0] = v0; dst[1] = v1;
    }
}

// ---------------- per-step recurrent GEMM, W from smem: out[16b x 8d] ----------------
// warp w: row-group rg = w>>1 (2 local rows), batch half bh = (w&1)*8 (8 batches)
__device__ __forceinline__ void gemm_rows_smem(const float* __restrict__ Wsm,   // 8 rows x 1024, smem
                                               const float* __restrict__ hw,    // global h (L1)
                                               float* sm_out) {
    const int tid = threadIdx.x;
    const int lane = tid & 31;
    const int wid = tid >> 5;
    const int rg = wid >> 1;
    const int bhalf = (wid & 1) << 3;
    const float4* W0 = (const float4*)(Wsm + (rg * 2) * D_);
    const float4* W1 = (const float4*)(Wsm + (rg * 2 + 1) * D_);
    const float4* H4 = (const float4*)hw;
    float acc0[8], acc1[8];
#pragma unroll
    for (int i = 0; i < 8; i++) { acc0[i] = 0.f; acc1[i] = 0.f; }
#pragma unroll
    for (int it = 0; it < 8; it++) {
        const int j = lane + (it << 5);
        const float4 w0 = W0[j];                 // LDS.128, conflict-free
        const float4 w1 = W1[j];
#pragma unroll
        for (int bb = 0; bb < 8; bb++) {
            const float4 h = H4[(bhalf + bb) * 256 + j];
            acc0[bb] = fmaf(w0.x, h.x, fmaf(w0.y, h.y, fmaf(w0.z, h.z, fmaf(w0.w, h.w, acc0[bb]))));
            acc1[bb] = fmaf(w1.x, h.x, fmaf(w1.y, h.y, fmaf(w1.z, h.z, fmaf(w1.w, h.w, acc1[bb]))));
        }
    }
#pragma unroll
    for (int off = 16; off; off >>= 1) {
#pragma unroll
        for (int bb = 0; bb < 8; bb++) {
            acc0[bb] += __shfl_xor_sync(0xffffffffu, acc0[bb], off);
            acc1[bb] += __shfl_xor_sync(0xffffffffu, acc1[bb], off);
        }
    }
    if (lane < 16) {
        const int rr = lane >> 3;
        const int bb = lane & 7;
        sm_out[(rg * 2 + rr) * 16 + bhalf + bb] = rr ? acc1[bb] : acc0[bb];
    }
}

__device__ __forceinline__ void softmax16_to_smem(const float* __restrict__ scores,
                                                  float* sm_attn) {
    const int b = threadIdx.x;     // threads 0..15: one batch each
    float s[16];
    float m = -1e30f;
#pragma unroll
    for (int n = 0; n < 16; n++) { s[n] = scores[b * 16 + n] * SCALE; m = fmaxf(m, s[n]); }
    float sum = 0.f;
#pragma unroll
    for (int n = 0; n < 16; n++) { s[n] = __expf(s[n] - m); sum += s[n]; }
    const float inv = 1.f / sum;
#pragma unroll
    for (int n = 0; n < 16; n++) sm_attn[b * 16 + n] = s[n] * inv;
}

// ---------------- persistent scan kernel ----------------
__global__ void __launch_bounds__(NTHR, 1) scan_kernel(const float* __restrict__ Wh,
                                                       const float* __restrict__ Wwr,
                                                       const float* __restrict__ bh,
                                                       float* __restrict__ out) {
    extern __shared__ __align__(16) float w_sm[];   // [0,8K): Wh rows; [8K,16K): Wwr rows
    float* whs = w_sm;
    float* wws = w_sm + 8 * D_;

    const int tid = threadIdx.x;
    const int bid = blockIdx.x;
    const int lane = tid & 31;
    const int r0 = bid * 8;       // this block's 8 d-rows

    __shared__ float attn_s[256];  // read attn (P2) then write attn (P4)
    __shared__ float sm_out[128];  // 8 rows x 16 batches GEMM results
    __shared__ float sm_ws[256];   // per-block write-score partials

    // ---- stage this CTA's weight rows into smem once (reused for all 512 steps) ----
    {
        const float4* src1 = (const float4*)(Wh + r0 * D_);
        const float4* src2 = (const float4*)(Wwr + r0 * D_);
        float4* dst1 = (float4*)whs;
        float4* dst2 = (float4*)wws;
#pragma unroll
        for (int i = 0; i < (8 * D_ / 4) / NTHR; i++) {       // 8 iters
            dst1[tid + i * NTHR] = src1[tid + i * NTHR];
            dst2[tid + i * NTHR] = src2[tid + i * NTHR];
        }
    }
    __syncthreads();

    unsigned int nbar = 0;

    for (int t = 0; t < T_; t++) {
        const int cur = t & 1;
        const int nxt = cur ^ 1;

        // ================= P2: read-attn + GEMM1 + activations + output =================
        if (tid < 16) softmax16_to_smem(g_rs[cur], attn_s);
        if (bid == 0) g_ws[nxt][tid] = 0.f;    // prepare ws buffer for step t+1 accumulation
        __syncthreads();

        gemm_rows_smem(whs, g_hwork[cur], sm_out);
        __syncthreads();

        if (tid < 128) {
            const int dl = tid >> 4, b = tid & 15;
            const int d = r0 + dl;
            const float sum = sm_out[dl * 16 + b];
            float rv = 0.f;
#pragma unroll
            for (int n = 0; n < 16; n++)
                rv = fmaf(attn_s[b * 16 + n], g_tape[(b * 16 + n) * D_ + d], rv);
            const float xp = g_xz[(b * T_ + t) * (2 * D_) + d];
            const float pre = xp + sum + rv + bh[d];
            const float hnew = tanhf(pre);
            g_hwork[nxt][b * D_ + d] = hnew;
            const float z = g_xz[(b * T_ + t) * (2 * D_) + D_ + d];
            const float u = z + rv + hnew;
            const float gate = u / (1.f + __expf(-u));
            out[(b * T_ + t) * D_ + d] = hnew * gate;
        }
        grid_sync(&nbar);

        // ================= P3: GEMM2 (write_val) + write-score partials =================
        sm_ws[tid] = 0.f;
        __syncthreads();

        gemm_rows_smem(wws, g_hwork[nxt], sm_out);
        __syncthreads();

        if (tid < 128) {
            const int dl = tid >> 4, b = tid & 15;
            const int d = r0 + dl;
            const float wv = sm_out[dl * 16 + b];
            g_wval[b * D_ + d] = wv;
#pragma unroll
            for (int n = 0; n < 16; n++)
                atomicAdd(&sm_ws[b * 16 + n], wv * g_tape[(b * 16 + n) * D_ + d]);
        }
        if (bid == 0) g_rs[cur][tid] = 0.f;    // prepare rs buffer for step t+1's accumulation
        __syncthreads();
        atomicAdd(&g_ws[cur][tid], sm_ws[tid]);
        grid_sync(&nbar);

        // ================= P4: write-attn softmax + tape update + next read scores =================
        if (tid < 16) softmax16_to_smem(g_ws[cur], attn_s);
        __syncthreads();

        {
            float4* tape4 = (float4*)g_tape;
            const float4* wval4 = (const float4*)g_wval;
            const float4* hw4 = (const float4*)g_hwork[nxt];
#pragma unroll
            for (int rep = 0; rep < 2; rep++) {
                const int idx = rep * (NBLK * NTHR) + bid * NTHR + tid;  // 0..65535 float4s
                const int bn = idx >> 8;          // warp-uniform
                const int b = bn >> 4;
                const int c = idx & 255;
                const float4 tv = tape4[idx];
                const float wa = attn_s[bn];
                const float4 wv = wval4[b * 256 + c];
                float4 nv;
                nv.x = tv.x + wa * (wv.x - tv.x);
                nv.y = tv.y + wa * (wv.y - tv.y);
                nv.z = tv.z + wa * (wv.z - tv.z);
                nv.w = tv.w + wa * (wv.w - tv.w);
                tape4[idx] = nv;
                const float4 h = hw4[b * 256 + c];
                float part = h.x * nv.x + h.y * nv.y + h.z * nv.z + h.w * nv.w;
#pragma unroll
                for (int off = 16; off; off >>= 1)
                    part += __shfl_xor_sync(0xffffffffu, part, off);
                if (lane == 0) atomicAdd(&g_rs[nxt][bn], part);
            }
        }
        grid_sync(&nbar);
    }

    // ---- h_tape_final: appended after output_all ----
    {
        float4* dst = (float4*)(out + B_ * T_ * D_);
        const float4* src = (const float4*)g_tape;
        for (int i = bid * NTHR + tid; i < (B_ * N_ * D_) / 4; i += NBLK * NTHR)
            dst[i] = src[i];
    }
}

// ---------------- launch (4 graph nodes total) ----------------
extern "C" void kernel_launch(void* const* d_in, const int* in_sizes, int n_in,
                              void* d_out, int out_size) {
    const float* x          = (const float*)d_in[0];
    const float* tape_init  = (const float*)d_in[1];
    const float* hwork_init = (const float*)d_in[2];
    const float* Wh         = (const float*)d_in[3];
    const float* Wxz        = (const float*)d_in[4];
    const float* bh         = (const float*)d_in[5];
    const float* Wwr        = (const float*)d_in[6];
    float* out = (float*)d_out;

    // Opt-in to 64KB dynamic smem for the scan kernel. Not a stream op; the
    // attribute persists process-wide after the first (uncaptured) call.
    cudaFuncSetAttribute(scan_kernel, cudaFuncAttributeMaxDynamicSharedMemorySize,
                         W_SMEM_BYTES);

    init_kernel<<<B_ * N_, 128>>>(tape_init, hwork_init);

    dim3 gg(2 * D_ / 128, (B_ * T_) / 128);   // (16, 64)
    xz_gemm<<<gg, 256>>>(x, Wxz);

    scan_kernel<<<NBLK, NTHR, W_SMEM_BYTES>>>(Wh, Wwr, bh, out);
}

// round 8
// speedup vs baseline: 1.6300x; 1.5971x over previous
#include <cuda_runtime.h>
#include <cstdint>

#define B_ 16
#define T_ 512
#define D_ 1024
#define N_ 16
#define SCALE 0.03125f   // 1/sqrt(1024)

#define NBLK 128
#define NTHR 256

// dynamic smem layout (floats):
//   [0, 8192)        Wh slice   (8 rows x 1024)
//   [8192, 16384)    Wwr slice  (8 rows x 1024)
//   [16384, 32768)   h buffer   (16 x 1024)          <- TMA bulk target
//   [32768, +2056)   tape slice tp[d*257 + bn], d=0..7, bn=0..255 (pad 257 vs banks)
#define OFF_WH   0
#define OFF_WW   8192
#define OFF_H    16384
#define OFF_TP   32768
#define DYN_FLOATS (32768 + 257 * 8)
#define DYN_BYTES  (DYN_FLOATS * 4)

// ---------------- device scratch ----------------
__device__ __align__(16) float g_xz[B_ * T_ * 2 * D_];   // [b, t, 2D] = x_proj | z
__device__ __align__(16) float g_hwork[2][B_ * D_];      // parity h_work (global exchange)
__device__ __align__(16) float g_rs[2][B_ * N_];         // read-score accumulators, parity
__device__ __align__(16) float g_ws[2][B_ * N_];         // write-score accumulators, parity
__device__ unsigned int g_bar;

// ---------------- grid barrier ----------------
__device__ __forceinline__ void grid_sync(unsigned int* nbar) {
    __syncthreads();
    if (threadIdx.x == 0) {
        *nbar += 1;
        const unsigned int target = (*nbar) * (unsigned int)NBLK;
        __threadfence();
        atomicAdd(&g_bar, 1u);
        while (*((volatile unsigned int*)&g_bar) < target) { __nanosleep(32); }
        __threadfence();
    }
    __syncthreads();
}

// ---------------- tiny PTX helpers ----------------
__device__ __forceinline__ void mbar_init(uint32_t a, uint32_t cnt) {
    asm volatile("mbarrier.init.shared.b64 [%0], %1;" :: "r"(a), "r"(cnt) : "memory");
}
__device__ __forceinline__ void mbar_expect_tx(uint32_t a, uint32_t bytes) {
    asm volatile("mbarrier.arrive.expect_tx.shared.b64 _, [%0], %1;" :: "r"(a), "r"(bytes) : "memory");
}
__device__ __forceinline__ void tma_bulk_g2s(uint32_t dst, const void* src, uint32_t bytes, uint32_t mbar) {
    asm volatile("cp.async.bulk.shared::cluster.global.mbarrier::complete_tx::bytes [%0], [%1], %2, [%3];"
                 :: "r"(dst), "l"(src), "r"(bytes), "r"(mbar) : "memory");
}
__device__ __forceinline__ void mbar_wait(uint32_t a, uint32_t parity) {
    uint32_t done;
    asm volatile("{\n\t.reg .pred p;\n\t"
                 "mbarrier.try_wait.parity.shared.b64 p, [%1], %2;\n\t"
                 "selp.b32 %0, 1, 0, p;\n\t}"
                 : "=r"(done) : "r"(a), "r"(parity) : "memory");
    if (!done) {
        asm volatile("{\n\t.reg .pred P1;\n\t"
                     "W_%=:\n\t"
                     "mbarrier.try_wait.parity.shared.b64 P1, [%0], %1;\n\t"
                     "@P1 bra.uni DN_%=;\n\t"
                     "bra.uni W_%=;\n\t"
                     "DN_%=:\n\t}"
                     :: "r"(a), "r"(parity) : "memory");
    }
}

// ---------------- init ----------------
__global__ void init_kernel(const float* __restrict__ tape_init,
                            const float* __restrict__ hwork_init) {
    const int p = blockIdx.x;          // 0..255 = b*16+n
    const int tid = threadIdx.x;       // 128 threads
    __shared__ float red[128];
    const int b = p >> 4;
    float part = 0.f;
    for (int i = tid; i < D_; i += 128)
        part += tape_init[p * D_ + i] * hwork_init[b * D_ + i];
    red[tid] = part;
    __syncthreads();
    for (int s = 64; s; s >>= 1) { if (tid < s) red[tid] += red[tid + s]; __syncthreads(); }
    if (tid == 0) g_rs[0][p] = red[0];
    if (p < B_) {
        for (int i = tid; i < D_; i += 128) g_hwork[0][p * D_ + i] = hwork_init[p * D_ + i];
    }
    if (p == 0) {
        if (tid == 0) g_bar = 0u;
        for (int i = tid; i < B_ * N_; i += 128) {
            g_rs[1][i] = 0.f; g_ws[0][i] = 0.f; g_ws[1][i] = 0.f;
        }
    }
}

// ---------------- xz = x @ W_xz^T ----------------
__global__ void __launch_bounds__(256, 2) xz_gemm(const float* __restrict__ A,
                                                  const float* __restrict__ Bw) {
    __shared__ float As[8][128];
    __shared__ float Bs[8][128];
    const int tid = threadIdx.x;
    const int tx = tid & 15, ty = tid >> 4;
    const int mBase = blockIdx.y * 128, nBase = blockIdx.x * 128;
    const int lr = tid >> 1;
    const int lc = (tid & 1) << 2;
    float acc[8][8];
#pragma unroll
    for (int i = 0; i < 8; i++)
#pragma unroll
        for (int j = 0; j < 8; j++) acc[i][j] = 0.f;

    const float* Aptr = A + (mBase + lr) * 1024 + lc;
    const float* Bptr = Bw + (nBase + lr) * 1024 + lc;

    for (int k0 = 0; k0 < 1024; k0 += 8) {
        const float4 a4 = *(const float4*)(Aptr + k0);
        const float4 b4 = *(const float4*)(Bptr + k0);
        As[lc + 0][lr] = a4.x; As[lc + 1][lr] = a4.y; As[lc + 2][lr] = a4.z; As[lc + 3][lr] = a4.w;
        Bs[lc + 0][lr] = b4.x; Bs[lc + 1][lr] = b4.y; Bs[lc + 2][lr] = b4.z; Bs[lc + 3][lr] = b4.w;
        __syncthreads();
#pragma unroll
        for (int kk = 0; kk < 8; kk++) {
            float ar[8], br[8];
#pragma unroll
            for (int i = 0; i < 8; i++) { ar[i] = As[kk][ty * 8 + i]; br[i] = Bs[kk][tx * 8 + i]; }
#pragma unroll
            for (int i = 0; i < 8; i++)
#pragma unroll
                for (int j = 0; j < 8; j++) acc[i][j] = fmaf(ar[i], br[j], acc[i][j]);
        }
        __syncthreads();
    }
#pragma unroll
    for (int i = 0; i < 8; i++) {
        const int m = mBase + ty * 8 + i;
        float4* dst = (float4*)(g_xz + m * 2048 + nBase + tx * 8);
        float4 v0, v1;
        v0.x = acc[i][0]; v0.y = acc[i][1]; v0.z = acc[i][2]; v0.w = acc[i][3];
        v1.x = acc[i][4]; v1.y = acc[i][5]; v1.z = acc[i][6]; v1.w = acc[i][7];
        dst[0] = v0; dst[1] = v1;
    }
}

// ---------------- recurrent GEMM: 8 d-rows x 16 batches, all operands in smem ----------------
// warp w: rows (w&1)*4..+3, batches (w>>1)*4..+3.  sm_out[r*16+b].
__device__ __forceinline__ void gemm8(const float* __restrict__ Wsm,
                                      const float* __restrict__ Hsm,
                                      float* __restrict__ sm_out) {
    const int lane = threadIdx.x & 31;
    const int w = threadIdx.x >> 5;
    const int rg = (w & 1) * 4;
    const int bg = (w >> 1) * 4;
    const float4* W4 = (const float4*)Wsm;
    const float4* H4 = (const float4*)Hsm;
    float acc[4][4];
#pragma unroll
    for (int r = 0; r < 4; r++)
#pragma unroll
        for (int bb = 0; bb < 4; bb++) acc[r][bb] = 0.f;

#pragma unroll
    for (int it = 0; it < 8; it++) {
        const int j = lane + it * 32;
        float4 wv[4], hv[4];
#pragma unroll
        for (int r = 0; r < 4; r++) wv[r] = W4[(rg + r) * 256 + j];
#pragma unroll
        for (int bb = 0; bb < 4; bb++) hv[bb] = H4[(bg + bb) * 256 + j];
#pragma unroll
        for (int r = 0; r < 4; r++)
#pragma unroll
            for (int bb = 0; bb < 4; bb++)
                acc[r][bb] = fmaf(wv[r].x, hv[bb].x,
                             fmaf(wv[r].y, hv[bb].y,
                             fmaf(wv[r].z, hv[bb].z,
                             fmaf(wv[r].w, hv[bb].w, acc[r][bb]))));
    }
#pragma unroll
    for (int off = 16; off; off >>= 1)
#pragma unroll
        for (int r = 0; r < 4; r++)
#pragma unroll
            for (int bb = 0; bb < 4; bb++)
                acc[r][bb] += __shfl_xor_sync(0xffffffffu, acc[r][bb], off);
    if (lane == 0) {
#pragma unroll
        for (int r = 0; r < 4; r++)
#pragma unroll
            for (int bb = 0; bb < 4; bb++)
                sm_out[(rg + r) * 16 + bg + bb] = acc[r][bb];
    }
}

__device__ __forceinline__ void softmax16(const float* __restrict__ scores, float* sm_attn) {
    const int b = threadIdx.x;     // threads 0..15
    float s[16];
    float m = -1e30f;
#pragma unroll
    for (int n = 0; n < 16; n++) { s[n] = scores[b * 16 + n] * SCALE; m = fmaxf(m, s[n]); }
    float sum = 0.f;
#pragma unroll
    for (int n = 0; n < 16; n++) { s[n] = __expf(s[n] - m); sum += s[n]; }
    const float inv = 1.f / sum;
#pragma unroll
    for (int n = 0; n < 16; n++) sm_attn[b * 16 + n] = s[n] * inv;
}

// ---------------- persistent scan ----------------
__global__ void __launch_bounds__(NTHR, 1) scan_kernel(const float* __restrict__ Wh,
                                                       const float* __restrict__ Wwr,
                                                       const float* __restrict__ bh,
                                                       const float* __restrict__ tape_init,
                                                       float* __restrict__ out) {
    extern __shared__ __align__(16) float dyn[];
    float* whs = dyn + OFF_WH;
    float* wws = dyn + OFF_WW;
    float* hs  = dyn + OFF_H;
    float* tp  = dyn + OFF_TP;      // tp[d*257 + bn]

    __shared__ float attn_s[256];
    __shared__ float wa_s[256];
    __shared__ float sm_out[128];   // GEMM result: [localrow*16 + b]
    __shared__ float hn_s[128];     // h_new stash: [d*16 + b]
    __shared__ float bh_s[8];
    __shared__ __align__(8) unsigned long long mbar[2];

    const int tid = threadIdx.x;
    const int bid = blockIdx.x;
    const int r0 = bid * 8;

    const uint32_t mb0 = (uint32_t)__cvta_generic_to_shared(&mbar[0]);
    const uint32_t mb1 = (uint32_t)__cvta_generic_to_shared(&mbar[1]);
    const uint32_t hs_addr = (uint32_t)__cvta_generic_to_shared(hs);

    // stage weight slices (coalesced, once)
    {
        const float4* s1 = (const float4*)(Wh + r0 * D_);
        const float4* s2 = (const float4*)(Wwr + r0 * D_);
        float4* d1 = (float4*)whs;
        float4* d2 = (float4*)wws;
#pragma unroll
        for (int i = 0; i < 8; i++) {       // 2048 float4 / 256 threads
            d1[tid + i * NTHR] = s1[tid + i * NTHR];
            d2[tid + i * NTHR] = s2[tid + i * NTHR];
        }
    }
    // stage tape slice: thread=bn loads its 8 d's
    {
        const float4* src = (const float4*)(tape_init + tid * D_ + r0);
        const float4 v0 = src[0], v1 = src[1];
        tp[0 * 257 + tid] = v0.x; tp[1 * 257 + tid] = v0.y;
        tp[2 * 257 + tid] = v0.z; tp[3 * 257 + tid] = v0.w;
        tp[4 * 257 + tid] = v1.x; tp[5 * 257 + tid] = v1.y;
        tp[6 * 257 + tid] = v1.z; tp[7 * 257 + tid] = v1.w;
    }
    if (tid < 8) bh_s[tid] = bh[r0 + tid];
    if (tid == 0) { mbar_init(mb0, 1); mbar_init(mb1, 1); }
    __syncthreads();

    // initial h stage
    if (tid == 0) {
        mbar_expect_tx(mb0, B_ * D_ * 4);
        tma_bulk_g2s(hs_addr, g_hwork[0], B_ * D_ * 4, mb0);
    }
    mbar_wait(mb0, 0);

    unsigned int nbar = 0;

    for (int t = 0; t < T_; t++) {
        const int cur = t & 1;
        const int nxt = cur ^ 1;

        // ========== P2: read softmax + GEMM1 + activations ==========
        float xp = 0.f, zz = 0.f;
        if (tid < 128) {                     // prefetch xz early (DRAM latency hidden by GEMM)
            const int d = tid & 7, b = tid >> 3;
            const float* base = g_xz + ((size_t)(b * T_ + t)) * (2 * D_) + r0 + d;
            xp = __ldg(base);
            zz = __ldg(base + D_);
        }
        if (tid < 16) softmax16(g_rs[cur], attn_s);
        if (bid == 0) g_ws[nxt][tid] = 0.f;   // free for step t+1's P3 accumulation

        gemm8(whs, hs, sm_out);
        __syncthreads();

        if (tid < 128) {
            const int d = tid & 7, b = tid >> 3;
            float rv = 0.f;
#pragma unroll
            for (int n = 0; n < 16; n++)
                rv = fmaf(attn_s[b * 16 + n], tp[d * 257 + b * 16 + n], rv);
            const float pre = xp + sm_out[d * 16 + b] + rv + bh_s[d];
            const float hnew = tanhf(pre);
            g_hwork[nxt][b * D_ + r0 + d] = hnew;
            hn_s[d * 16 + b] = hnew;
            const float u = zz + rv + hnew;
            const float gate = u / (1.f + __expf(-u));
            out[((size_t)(b * T_ + t)) * D_ + r0 + d] = hnew * gate;
        }
        grid_sync(&nbar);

        // ========== P3: stage h_new (TMA) + GEMM2 + write-score partials ==========
        if (tid == 0) {
            mbar_expect_tx(mb1, B_ * D_ * 4);
            tma_bulk_g2s(hs_addr, g_hwork[nxt], B_ * D_ * 4, mb1);
        }
        if (bid == 0) g_rs[cur][tid] = 0.f;   // free for step t+1's P4 accumulation
        mbar_wait(mb1, (uint32_t)(t & 1));

        gemm8(wws, hs, sm_out);
        __syncthreads();

        {   // thread = bn: ws partial over own 8 d's (all smem) + one RED
            const int b = tid >> 4;
            float part = 0.f;
#pragma unroll
            for (int d = 0; d < 8; d++)
                part = fmaf(sm_out[d * 16 + b], tp[d * 257 + tid], part);
            atomicAdd(&g_ws[cur][tid], part);
        }
        grid_sync(&nbar);

        // ========== P4: write softmax + tape update + next read scores ==========
        if (tid < 16) softmax16(g_ws[cur], wa_s);
        __syncthreads();

        {   // thread = bn: update own d-slice of tape, accumulate rs for next step
            const int b = tid >> 4;
            const float wa = wa_s[tid];
            float part = 0.f;
#pragma unroll
            for (int d = 0; d < 8; d++) {
                const float tv = tp[d * 257 + tid];
                const float wv = sm_out[d * 16 + b];
                const float nv = fmaf(wa, wv - tv, tv);
                tp[d * 257 + tid] = nv;
                part = fmaf(hn_s[d * 16 + b], nv, part);
            }
            atomicAdd(&g_rs[nxt][tid], part);
        }
        grid_sync(&nbar);
    }

    // ---- h_tape_final: tape slice -> out tail ----
    {
        float* dst = out + (size_t)B_ * T_ * D_ + (size_t)tid * D_ + r0;
        float4 v0, v1;
        v0.x = tp[0 * 257 + tid]; v0.y = tp[1 * 257 + tid];
        v0.z = tp[2 * 257 + tid]; v0.w = tp[3 * 257 + tid];
        v1.x = tp[4 * 257 + tid]; v1.y = tp[5 * 257 + tid];
        v1.z = tp[6 * 257 + tid]; v1.w = tp[7 * 257 + tid];
        ((float4*)dst)[0] = v0;
        ((float4*)dst)[1] = v1;
    }
}

// ---------------- launch (3 graph nodes) ----------------
extern "C" void kernel_launch(void* const* d_in, const int* in_sizes, int n_in,
                              void* d_out, int out_size) {
    const float* x          = (const float*)d_in[0];
    const float* tape_init  = (const float*)d_in[1];
    const float* hwork_init = (const float*)d_in[2];
    const float* Wh         = (const float*)d_in[3];
    const float* Wxz        = (const float*)d_in[4];
    const float* bh         = (const float*)d_in[5];
    const float* Wwr        = (const float*)d_in[6];
    float* out = (float*)d_out;

    cudaFuncSetAttribute(scan_kernel, cudaFuncAttributeMaxDynamicSharedMemorySize,
                         DYN_BYTES);

    init_kernel<<<B_ * N_, 128>>>(tape_init, hwork_init);

    dim3 gg(2 * D_ / 128, (B_ * T_) / 128);   // (16, 64)
    xz_gemm<<<gg, 256>>>(x, Wxz);

    scan_kernel<<<NBLK, NTHR, DYN_BYTES>>>(Wh, Wwr, bh, tape_init, out);
}